// round 1
// baseline (speedup 1.0000x reference)
#include <cuda_runtime.h>

#define Nn 8192
#define IN_F 256
#define OUT_F 128
#define ALPHA 0.2f

#define BM 32
#define BN 128
#define PSTRIDE 132   // padded P row stride (floats) to avoid bank conflicts

// Scratch (device globals — no allocation allowed)
__device__ float g_Wh[Nn * OUT_F];
__device__ float g_f1[Nn];
__device__ float g_f2[Nn];
__device__ float g_f2max;

// ---------------------------------------------------------------------------
// Kernel 1: Wh = h @ W ; f1 = Wh @ a1 ; f2 = Wh @ a2.  One row per 128-thread block.
// ---------------------------------------------------------------------------
__global__ __launch_bounds__(128) void k_proj(const float* __restrict__ h,
                                              const float* __restrict__ W,
                                              const float* __restrict__ a) {
    __shared__ float h_s[IN_F];
    __shared__ float r1[4], r2[4];
    const int row = blockIdx.x;
    const int t = threadIdx.x;  // 0..127 = output feature

    h_s[t]       = h[row * IN_F + t];
    h_s[t + 128] = h[row * IN_F + t + 128];
    __syncthreads();

    float acc = 0.f;
#pragma unroll 8
    for (int k = 0; k < IN_F; k++)
        acc = fmaf(h_s[k], __ldg(&W[k * OUT_F + t]), acc);

    g_Wh[row * OUT_F + t] = acc;

    float s1 = acc * __ldg(&a[t]);
    float s2 = acc * __ldg(&a[OUT_F + t]);
#pragma unroll
    for (int o = 16; o; o >>= 1) {
        s1 += __shfl_xor_sync(0xFFFFFFFFu, s1, o);
        s2 += __shfl_xor_sync(0xFFFFFFFFu, s2, o);
    }
    const int w = t >> 5, lane = t & 31;
    if (lane == 0) { r1[w] = s1; r2[w] = s2; }
    __syncthreads();
    if (t == 0) {
        g_f1[row] = r1[0] + r1[1] + r1[2] + r1[3];
        g_f2[row] = r2[0] + r2[1] + r2[2] + r2[3];
    }
}

// ---------------------------------------------------------------------------
// Kernel 2: global max of f2 (single block)
// ---------------------------------------------------------------------------
__global__ __launch_bounds__(256) void k_f2max() {
    __shared__ float red[256];
    float m = -3.4e38f;
    for (int i = threadIdx.x; i < Nn; i += 256) m = fmaxf(m, g_f2[i]);
    red[threadIdx.x] = m;
    __syncthreads();
#pragma unroll
    for (int s = 128; s; s >>= 1) {
        if (threadIdx.x < s) red[threadIdx.x] = fmaxf(red[threadIdx.x], red[threadIdx.x + s]);
        __syncthreads();
    }
    if (threadIdx.x == 0) g_f2max = red[0];
}

// ---------------------------------------------------------------------------
// Kernel 3: fused masked-softmax attention + PV GEMM.
//   Block: 256 threads, BM=32 rows. Loop over 64 j-tiles of BN=128.
//   Phase A: P tile (exp of masked lrelu scores, shifted by per-row bound M_i).
//   Phase B: acc[32x128] += P[32x128] @ WhTile[128x128] (4x4 register micro-tiles).
// ---------------------------------------------------------------------------
extern __shared__ char smem_raw[];

__global__ __launch_bounds__(256) void k_attn(const int* __restrict__ adj,
                                              float* __restrict__ out) {
    float* wh_s = (float*)smem_raw;                       // BN * OUT_F = 64 KB
    float* p_s  = (float*)(smem_raw + BN * OUT_F * 4);    // BM * PSTRIDE = 16.9 KB
    float* l_s  = (float*)(smem_raw + BN * OUT_F * 4 + BM * PSTRIDE * 4);  // BM floats

    const int i0  = blockIdx.x * BM;
    const int tid = threadIdx.x;

    // ---- Phase-A thread mapping: 8 threads per row ----
    const int arow  = tid >> 3;        // 0..31 local row
    const int acol0 = (tid & 7) * 4;   // base col within 32-col stripe
    const float f1v = g_f1[i0 + arow];
    float m_i = f1v + g_f2max;
    m_i = (m_i > 0.f) ? m_i : ALPHA * m_i;   // lrelu of the score upper bound
    float lsum = 0.f;

    // ---- GEMM thread mapping: ty rows (x4), tx features (x4) ----
    const int ty = tid >> 5;   // 0..7 -> rows ty*4 .. ty*4+3
    const int tx = tid & 31;   // 0..31 -> feats tx*4 .. tx*4+3
    float acc[4][4] = {};

    for (int j0 = 0; j0 < Nn; j0 += BN) {
        __syncthreads();   // previous GEMM done reading smem

        // Load Wh tile [BN x OUT_F] -> smem (4096 float4, 16 per thread)
        {
            const float4* src = (const float4*)(g_Wh + (size_t)j0 * OUT_F);
            float4* dst = (float4*)wh_s;
#pragma unroll
            for (int k = 0; k < 16; k++)
                dst[tid + k * 256] = src[tid + k * 256];
        }

        // Phase A: scores -> P tile
#pragma unroll
        for (int c = 0; c < 4; c++) {
            const int col = c * 32 + acol0;
            const int4  av  = *(const int4*)(adj + (size_t)(i0 + arow) * Nn + j0 + col);
            const float4 fv = *(const float4*)(g_f2 + j0 + col);
            float4 p;
            float s;
            s = f1v + fv.x; s = (s > 0.f) ? s : ALPHA * s; p.x = (av.x > 0) ? __expf(s - m_i) : 0.f;
            s = f1v + fv.y; s = (s > 0.f) ? s : ALPHA * s; p.y = (av.y > 0) ? __expf(s - m_i) : 0.f;
            s = f1v + fv.z; s = (s > 0.f) ? s : ALPHA * s; p.z = (av.z > 0) ? __expf(s - m_i) : 0.f;
            s = f1v + fv.w; s = (s > 0.f) ? s : ALPHA * s; p.w = (av.w > 0) ? __expf(s - m_i) : 0.f;
            lsum += (p.x + p.y) + (p.z + p.w);
            *(float4*)(p_s + arow * PSTRIDE + col) = p;
        }

        __syncthreads();

        // Phase B: GEMM  acc += P @ WhTile
#pragma unroll 4
        for (int jj = 0; jj < BN; jj++) {
            const float4 wv = *(const float4*)(wh_s + jj * OUT_F + tx * 4);
#pragma unroll
            for (int r = 0; r < 4; r++) {
                const float pv = p_s[(ty * 4 + r) * PSTRIDE + jj];
                acc[r][0] = fmaf(pv, wv.x, acc[r][0]);
                acc[r][1] = fmaf(pv, wv.y, acc[r][1]);
                acc[r][2] = fmaf(pv, wv.z, acc[r][2]);
                acc[r][3] = fmaf(pv, wv.w, acc[r][3]);
            }
        }
    }

    // Row-sum reduction across the 8 phase-A threads of each row (adjacent lanes)
#pragma unroll
    for (int o = 1; o < 8; o <<= 1) lsum += __shfl_xor_sync(0xFFFFFFFFu, lsum, o);
    if ((tid & 7) == 0) l_s[arow] = lsum;
    __syncthreads();

    // Normalize and store
#pragma unroll
    for (int r = 0; r < 4; r++) {
        const int row = ty * 4 + r;
        const float inv = 1.f / l_s[row];
        float4 o4;
        o4.x = acc[r][0] * inv;
        o4.y = acc[r][1] * inv;
        o4.z = acc[r][2] * inv;
        o4.w = acc[r][3] * inv;
        *(float4*)(out + (size_t)(i0 + row) * OUT_F + tx * 4) = o4;
    }
}

// ---------------------------------------------------------------------------
extern "C" void kernel_launch(void* const* d_in, const int* in_sizes, int n_in,
                              void* d_out, int out_size) {
    const float* h   = (const float*)d_in[0];
    const int*   adj = (const int*)d_in[1];
    const float* W   = (const float*)d_in[2];
    const float* a   = (const float*)d_in[3];
    float* out = (float*)d_out;

    static int smem_set = 0;
    const int smem_bytes = BN * OUT_F * 4 + BM * PSTRIDE * 4 + BM * 4;  // ~82.6 KB
    if (!smem_set) {
        cudaFuncSetAttribute(k_attn, cudaFuncAttributeMaxDynamicSharedMemorySize, smem_bytes);
        smem_set = 1;
    }

    k_proj<<<Nn, 128>>>(h, W, a);
    k_f2max<<<1, 256>>>();
    k_attn<<<Nn / BM, 256, smem_bytes>>>(adj, out);
}

// round 3
// speedup vs baseline: 3.2395x; 3.2395x over previous
#include <cuda_runtime.h>
#include <cuda_bf16.h>
#include <cstdint>

#define Nn 8192
#define IN_F 256
#define OUT_F 128
#define ALPHA 0.2f
#define SPLIT 2
#define JHALF (Nn / SPLIT) /* 4096 */
#define BK 64
#define NST (JHALF / BK)   /* 64 stages */

#define STRIDE 72          /* bf16 elems per row (64 data + 8 pad) */
#define STRIDE_B (STRIDE * 2) /* 144 bytes */
#define TILE_B (128 * STRIDE_B)   /* 18432 B per tile */
#define STAGE_B (4 * TILE_B)      /* Phi,Plo,Bhi,Blo = 73728 B */

// ---------------- scratch (device globals; no allocation allowed) ------------
__device__ float g_f1[Nn];
__device__ float g_f2[Nn];
__device__ float g_f2max;
__device__ __nv_bfloat16 g_WhT_hi[OUT_F * Nn];   // transposed [feat][row]
__device__ __nv_bfloat16 g_WhT_lo[OUT_F * Nn];
__device__ float g_np0[Nn * OUT_F];              // partial numerators
__device__ float g_np1[Nn * OUT_F];
__device__ float g_lp0[Nn];                      // partial row sums
__device__ float g_lp1[Nn];

// ---------------- helpers ----------------------------------------------------
__device__ __forceinline__ uint32_t smem_to_u32(const void* p) {
    uint32_t a;
    asm("{ .reg .u64 t; cvta.to.shared.u64 t, %1; cvt.u32.u64 %0, t; }" : "=r"(a) : "l"(p));
    return a;
}

__device__ __forceinline__ void ldsm4(uint32_t* r, uint32_t addr) {
    asm volatile("ldmatrix.sync.aligned.m8n8.x4.shared.b16 {%0,%1,%2,%3}, [%4];"
                 : "=r"(r[0]), "=r"(r[1]), "=r"(r[2]), "=r"(r[3]) : "r"(addr));
}

__device__ __forceinline__ void mma16816(float* d, const uint32_t* a, uint32_t b0, uint32_t b1) {
    asm volatile("mma.sync.aligned.m16n8k16.row.col.f32.bf16.bf16.f32 "
                 "{%0,%1,%2,%3},{%4,%5,%6,%7},{%8,%9},{%0,%1,%2,%3};"
                 : "+f"(d[0]), "+f"(d[1]), "+f"(d[2]), "+f"(d[3])
                 : "r"(a[0]), "r"(a[1]), "r"(a[2]), "r"(a[3]), "r"(b0), "r"(b1));
}

#define CPASYNC16(dst, src) \
    asm volatile("cp.async.cg.shared.global [%0], [%1], 16;" :: "r"(dst), "l"(src))
#define CP_COMMIT() asm volatile("cp.async.commit_group;")
#define CP_WAIT0()  asm volatile("cp.async.wait_group 0;" ::: "memory")

// ---------------------------------------------------------------------------
// Kernel 1: tiled GEMM  Wh = h@W ; emits g_f1, g_f2, transposed bf16 hi/lo WhT.
// ---------------------------------------------------------------------------
__global__ __launch_bounds__(256) void k_proj(const float* __restrict__ h,
                                              const float* __restrict__ W,
                                              const float* __restrict__ a) {
    __shared__ float w_s[32 * 128];
    __shared__ float h_s[32 * 33];
    const int tid = threadIdx.x;
    const int i0 = blockIdx.x * 32;
    const int row = tid >> 3;
    const int f0 = (tid & 7) * 16;
    float acc[16];
#pragma unroll
    for (int j = 0; j < 16; j++) acc[j] = 0.f;

    for (int kc = 0; kc < IN_F; kc += 32) {
        __syncthreads();
        const float4* wsrc = (const float4*)(W + kc * OUT_F);
#pragma unroll
        for (int u = 0; u < 4; u++) ((float4*)w_s)[tid + u * 256] = wsrc[tid + u * 256];
        {
            const int kk = (tid & 7) * 4;
            float4 hv = *(const float4*)(h + (size_t)(i0 + row) * IN_F + kc + kk);
            h_s[row * 33 + kk + 0] = hv.x;
            h_s[row * 33 + kk + 1] = hv.y;
            h_s[row * 33 + kk + 2] = hv.z;
            h_s[row * 33 + kk + 3] = hv.w;
        }
        __syncthreads();
#pragma unroll
        for (int kk = 0; kk < 32; kk++) {
            const float hval = h_s[row * 33 + kk];
            const float* wrow = w_s + kk * 128 + f0;
#pragma unroll
            for (int j = 0; j < 16; j++) acc[j] = fmaf(hval, wrow[j], acc[j]);
        }
    }

    float s1 = 0.f, s2 = 0.f;
#pragma unroll
    for (int j = 0; j < 16; j++) {
        s1 = fmaf(acc[j], __ldg(&a[f0 + j]), s1);
        s2 = fmaf(acc[j], __ldg(&a[OUT_F + f0 + j]), s2);
    }
#pragma unroll
    for (int o = 1; o < 8; o <<= 1) {
        s1 += __shfl_xor_sync(0xFFFFFFFFu, s1, o);
        s2 += __shfl_xor_sync(0xFFFFFFFFu, s2, o);
    }
    if ((tid & 7) == 0) { g_f1[i0 + row] = s1; g_f2[i0 + row] = s2; }

    __syncthreads();
#pragma unroll
    for (int j = 0; j < 16; j++) w_s[row * 128 + f0 + j] = acc[j];
    __syncthreads();

    const int f = tid & 127;
    const int arr = tid >> 7;   // 0 = hi, 1 = lo
    uint32_t pk[16];
#pragma unroll
    for (int rp = 0; rp < 16; rp++) {
        float v0 = w_s[(2 * rp) * 128 + f];
        float v1 = w_s[(2 * rp + 1) * 128 + f];
        __nv_bfloat16 b0, b1;
        if (arr == 0) {
            b0 = __float2bfloat16_rn(v0);
            b1 = __float2bfloat16_rn(v1);
        } else {
            __nv_bfloat16 t0 = __float2bfloat16_rn(v0), t1 = __float2bfloat16_rn(v1);
            b0 = __float2bfloat16_rn(v0 - __bfloat162float(t0));
            b1 = __float2bfloat16_rn(v1 - __bfloat162float(t1));
        }
        pk[rp] = ((uint32_t)__bfloat16_as_ushort(b1) << 16) | (uint32_t)__bfloat16_as_ushort(b0);
    }
    __nv_bfloat16* dst = (arr == 0 ? g_WhT_hi : g_WhT_lo) + (size_t)f * Nn + i0;
#pragma unroll
    for (int q = 0; q < 4; q++)
        ((uint4*)dst)[q] = make_uint4(pk[4 * q], pk[4 * q + 1], pk[4 * q + 2], pk[4 * q + 3]);
}

// ---------------------------------------------------------------------------
// Kernel 2: global max of f2
// ---------------------------------------------------------------------------
__global__ __launch_bounds__(256) void k_f2max() {
    __shared__ float red[256];
    float m = -3.4e38f;
    for (int i = threadIdx.x; i < Nn; i += 256) m = fmaxf(m, g_f2[i]);
    red[threadIdx.x] = m;
    __syncthreads();
#pragma unroll
    for (int s = 128; s; s >>= 1) {
        if (threadIdx.x < s) red[threadIdx.x] = fmaxf(red[threadIdx.x], red[threadIdx.x + s]);
        __syncthreads();
    }
    if (threadIdx.x == 0) g_f2max = red[0];
}

// ---------------------------------------------------------------------------
// Kernel 3: fused masked-softmax + HMMA PV GEMM (bf16 hi/lo, fp32 accum).
// 512 threads = 16 warps (4x4). Warp tile 32x32. Double buffer, 1 sync/stage.
// ---------------------------------------------------------------------------
#define SMEM_ATTN (2 * STAGE_B + 1024)

__global__ __launch_bounds__(512, 1) void k_attn(const int* __restrict__ adj) {
    extern __shared__ char smem_raw[];
    const uint32_t raw_u32 = smem_to_u32(smem_raw);
    const uint32_t base_u32 = (raw_u32 + 127u) & ~127u;
    char* base = smem_raw + (base_u32 - raw_u32);
    float* l_s = (float*)(base + 2 * STAGE_B);

    const int tid = threadIdx.x;
    const int rb = blockIdx.x >> 1;
    const int half = blockIdx.x & 1;
    const int i0 = rb * 128;
    const int jh = half * JHALF;

    // phase-A mapping: 4 threads per row, 16 cols each
    const int arow = tid >> 2;
    const int acol0 = (tid & 3) * 16;
    const size_t adjrow = (size_t)(i0 + arow) * Nn;
    const float f1v = g_f1[i0 + arow];
    float m_i = f1v + g_f2max;
    m_i = (m_i > 0.f) ? m_i : ALPHA * m_i;
    float lsum = 0.f;

    // warp mapping for MMA: 4x4 warps, tile 32x32
    const int wid = tid >> 5, lane = tid & 31;
    const int wm = wid >> 2, wn = wid & 3;
    float acc[2][4][4];
#pragma unroll
    for (int mt = 0; mt < 2; mt++)
#pragma unroll
        for (int nt = 0; nt < 4; nt++)
#pragma unroll
            for (int q = 0; q < 4; q++) acc[mt][nt][q] = 0.f;

    // ldmatrix lane address components (precomputed)
    const uint32_t a_row = wm * 32 + (lane & 15);
    const uint32_t a_kofs = ((lane >> 4) << 3) * 2;                 // bytes
    const uint32_t b_n = wn * 32 + (lane & 7) + ((lane >> 4) & 1) * 8;
    const uint32_t b_kofs = (((lane >> 3) & 1) << 3) * 2;           // bytes

    // preload stage 0 adj/f2
    int4 av[4];
    float4 fv[4];
#pragma unroll
    for (int c = 0; c < 4; c++) {
        const int col = acol0 + c * 4;
        av[c] = *(const int4*)(adj + adjrow + jh + col);
        fv[c] = *(const float4*)(g_f2 + jh + col);
    }

    for (int s = 0; s < NST; s++) {
        const int b = s & 1;
        const uint32_t buf = base_u32 + b * STAGE_B;
        const uint32_t phi = buf;
        const uint32_t plo = buf + TILE_B;
        const uint32_t bhi = buf + 2 * TILE_B;
        const uint32_t blo = buf + 3 * TILE_B;
        const int j0 = jh + s * BK;

        // ---- B tiles via cp.async (2 uint4 per thread per array) ----
#pragma unroll
        for (int q = 0; q < 2; q++) {
            const int u = tid + q * 512;
            const int f = u >> 3, up = u & 7;
            const uint32_t doff = (uint32_t)f * STRIDE_B + up * 16;
            const __nv_bfloat16* srch = g_WhT_hi + (size_t)f * Nn + j0 + up * 8;
            const __nv_bfloat16* srcl = g_WhT_lo + (size_t)f * Nn + j0 + up * 8;
            CPASYNC16(bhi + doff, srch);
            CPASYNC16(blo + doff, srcl);
        }
        CP_COMMIT();

        // ---- P tile: masked lrelu -> exp -> bf16 hi/lo (from preloaded regs) ----
#pragma unroll
        for (int c = 0; c < 4; c++) {
            const int col = acol0 + c * 4;
            float p0, p1, p2, p3, sc;
            sc = f1v + fv[c].x; sc = sc > 0.f ? sc : ALPHA * sc; p0 = av[c].x > 0 ? __expf(sc - m_i) : 0.f;
            sc = f1v + fv[c].y; sc = sc > 0.f ? sc : ALPHA * sc; p1 = av[c].y > 0 ? __expf(sc - m_i) : 0.f;
            sc = f1v + fv[c].z; sc = sc > 0.f ? sc : ALPHA * sc; p2 = av[c].z > 0 ? __expf(sc - m_i) : 0.f;
            sc = f1v + fv[c].w; sc = sc > 0.f ? sc : ALPHA * sc; p3 = av[c].w > 0 ? __expf(sc - m_i) : 0.f;
            lsum += (p0 + p1) + (p2 + p3);

            __nv_bfloat16 h0 = __float2bfloat16_rn(p0), h1 = __float2bfloat16_rn(p1);
            __nv_bfloat16 h2 = __float2bfloat16_rn(p2), h3 = __float2bfloat16_rn(p3);
            uint32_t hi01 = ((uint32_t)__bfloat16_as_ushort(h1) << 16) | __bfloat16_as_ushort(h0);
            uint32_t hi23 = ((uint32_t)__bfloat16_as_ushort(h3) << 16) | __bfloat16_as_ushort(h2);
            __nv_bfloat16 q0 = __float2bfloat16_rn(p0 - __bfloat162float(h0));
            __nv_bfloat16 q1 = __float2bfloat16_rn(p1 - __bfloat162float(h1));
            __nv_bfloat16 q2 = __float2bfloat16_rn(p2 - __bfloat162float(h2));
            __nv_bfloat16 q3 = __float2bfloat16_rn(p3 - __bfloat162float(h3));
            uint32_t lo01 = ((uint32_t)__bfloat16_as_ushort(q1) << 16) | __bfloat16_as_ushort(q0);
            uint32_t lo23 = ((uint32_t)__bfloat16_as_ushort(q3) << 16) | __bfloat16_as_ushort(q2);

            const uint32_t off = (uint32_t)arow * STRIDE_B + col * 2;
            *(uint2*)(base + (b * STAGE_B) + off) = make_uint2(hi01, hi23);
            *(uint2*)(base + (b * STAGE_B) + TILE_B + off) = make_uint2(lo01, lo23);
        }

        // ---- preload next stage adj/f2 (latency hides under MMA) ----
        if (s + 1 < NST) {
            const int jn = j0 + BK;
#pragma unroll
            for (int c = 0; c < 4; c++) {
                const int col = acol0 + c * 4;
                av[c] = *(const int4*)(adj + adjrow + jn + col);
                fv[c] = *(const float4*)(g_f2 + jn + col);
            }
        }

        CP_WAIT0();
        __syncthreads();

        // ---- MMA from buf b ----
#pragma unroll
        for (int ks = 0; ks < 4; ks++) {
            const uint32_t akb = (uint32_t)(ks * 16) * 2 + a_kofs;
            const uint32_t bkb = (uint32_t)(ks * 16) * 2 + b_kofs;
            uint32_t Ah[2][4], Al[2][4], Bh[2][4], Bl[2][4];
            ldsm4(Ah[0], phi + a_row * STRIDE_B + akb);
            ldsm4(Ah[1], phi + (a_row + 16) * STRIDE_B + akb);
            ldsm4(Al[0], plo + a_row * STRIDE_B + akb);
            ldsm4(Al[1], plo + (a_row + 16) * STRIDE_B + akb);
            ldsm4(Bh[0], bhi + b_n * STRIDE_B + bkb);
            ldsm4(Bh[1], bhi + (b_n + 16) * STRIDE_B + bkb);
            ldsm4(Bl[0], blo + b_n * STRIDE_B + bkb);
            ldsm4(Bl[1], blo + (b_n + 16) * STRIDE_B + bkb);
#pragma unroll
            for (int mt = 0; mt < 2; mt++) {
#pragma unroll
                for (int n16 = 0; n16 < 2; n16++) {
#pragma unroll
                    for (int hh = 0; hh < 2; hh++) {
                        const int nt = n16 * 2 + hh;
                        const uint32_t bh0 = Bh[n16][hh * 2], bh1 = Bh[n16][hh * 2 + 1];
                        const uint32_t bl0 = Bl[n16][hh * 2], bl1 = Bl[n16][hh * 2 + 1];
                        mma16816(acc[mt][nt], Ah[mt], bh0, bh1);
                        mma16816(acc[mt][nt], Ah[mt], bl0, bl1);
                        mma16816(acc[mt][nt], Al[mt], bh0, bh1);
                    }
                }
            }
        }
    }

    // ---- row-sum reduction (4 threads/row) ----
#pragma unroll
    for (int o = 1; o < 4; o <<= 1) lsum += __shfl_xor_sync(0xFFFFFFFFu, lsum, o);
    if ((tid & 3) == 0) l_s[arow] = lsum;
    __syncthreads();
    if (tid < 128) (half ? g_lp1 : g_lp0)[i0 + tid] = l_s[tid];

    // ---- write partial numerators ----
    float* np = (half ? g_np1 : g_np0);
#pragma unroll
    for (int mt = 0; mt < 2; mt++) {
#pragma unroll
        for (int nt = 0; nt < 4; nt++) {
            const int r0 = i0 + wm * 32 + mt * 16 + (lane >> 2);
            const int cc = wn * 32 + nt * 8 + (lane & 3) * 2;
            *(float2*)(np + (size_t)r0 * OUT_F + cc) = make_float2(acc[mt][nt][0], acc[mt][nt][1]);
            *(float2*)(np + (size_t)(r0 + 8) * OUT_F + cc) = make_float2(acc[mt][nt][2], acc[mt][nt][3]);
        }
    }
}

// ---------------------------------------------------------------------------
// Kernel 4: combine halves, normalize
// ---------------------------------------------------------------------------
__global__ __launch_bounds__(256) void k_norm(float* __restrict__ out) {
    const int idx = blockIdx.x * 256 + threadIdx.x;  // float4 index
    const int i = idx >> 5;                          // row
    const float inv = 1.f / (g_lp0[i] + g_lp1[i]);
    const float4 x = ((const float4*)g_np0)[idx];
    const float4 y = ((const float4*)g_np1)[idx];
    ((float4*)out)[idx] = make_float4((x.x + y.x) * inv, (x.y + y.y) * inv,
                                      (x.z + y.z) * inv, (x.w + y.w) * inv);
}

// ---------------------------------------------------------------------------
extern "C" void kernel_launch(void* const* d_in, const int* in_sizes, int n_in,
                              void* d_out, int out_size) {
    const float* h   = (const float*)d_in[0];
    const int*   adj = (const int*)d_in[1];
    const float* W   = (const float*)d_in[2];
    const float* a   = (const float*)d_in[3];
    float* out = (float*)d_out;

    static int smem_set = 0;
    if (!smem_set) {
        cudaFuncSetAttribute(k_attn, cudaFuncAttributeMaxDynamicSharedMemorySize, SMEM_ATTN);
        smem_set = 1;
    }

    k_proj<<<Nn / 32, 256>>>(h, W, a);
    k_f2max<<<1, 256>>>();
    k_attn<<<(Nn / 128) * SPLIT, 512, SMEM_ATTN>>>(adj);
    k_norm<<<Nn * OUT_F / 4 / 256, 256>>>(out);
}